// round 15
// baseline (speedup 1.0000x reference)
#include <cuda_runtime.h>
#include <cstdint>

// Decode-mode paged attention, fp32, GQA 4. Split-KV flash decode, fully fused.
// Token x head lane mapping: each lane owns (token = lane>>2 within warp's 8, head = lane&3),
// so K smem + V L1 traffic is 1x per CTA (was 4x). Triple-buffered cp.async pipeline,
// V L1 prefetch, last-CTA-per-(b,kvh) fused reduction.

#define BB     32
#define HH     32
#define DD     128
#define KVHH   8
#define GG     4
#define NPAGE  2048
#define TT     64
#define PPSS   64
#define NSPLIT 16
#define PPER   (PPSS / NSPLIT)     // 4 pages per split
#define TOKSPL (PPER * TT)         // 256 tokens per split
#define TILE   32                  // tokens per smem tile (half page)
#define NBUF   3
#define L2E    1.4426950408889634f
#define FULL   0xffffffffu

__device__ float g_m[NSPLIT * BB * HH];
__device__ float g_l[NSPLIT * BB * HH];
__device__ float g_o[NSPLIT * BB * HH * DD];
__device__ int   g_cnt[BB * KVHH];          // zero-init; last CTA resets -> replay-safe

__device__ __forceinline__ void cp16(uint32_t dst, const void* src) {
    asm volatile("cp.async.cg.shared.global [%0], [%1], 16;\n" :: "r"(dst), "l"(src));
}
__device__ __forceinline__ void fma4(float4& o, float p, float4 v) {
    o.x += p * v.x; o.y += p * v.y; o.z += p * v.z; o.w += p * v.w;
}
__device__ __forceinline__ void mul4(float4& o, float r) {
    o.x *= r; o.y *= r; o.z *= r; o.w *= r;
}

__global__ __launch_bounds__(128, 4)
void attn_fused(const float* __restrict__ q,
                const float* __restrict__ kp,
                const float* __restrict__ vp,
                const int*   __restrict__ lengths,
                const int*   __restrict__ pidx,
                float*       __restrict__ out)
{
    // K tile triple buffer: [3][token 0..31][chunk 0..31] float4, XOR-swizzled
    __shared__ float4 ksm[NBUF][TILE * 32];   // 48 KB
    __shared__ float4 qs[GG][32];             // q[head][chunk]
    __shared__ float4 psm[GG][8];             // p[warp][tok] = (h0,h1,h2,h3)
    __shared__ float  msm[GG][GG], lsm[GG][GG];
    __shared__ int    s_last;
    // osm aliases ksm[0] (8 KB needed, 16 KB available) -- used only after pipeline drains
    float4 (*osm)[GG][32] = (float4 (*)[GG][32])&ksm[0][0];

    const int split = blockIdx.x;
    const int kvh   = blockIdx.y;
    const int b     = blockIdx.z;
    const int tid   = threadIdx.x;
    const int warp  = tid >> 5;
    const int lane  = tid & 31;
    const int hd    = lane & 3;              // head (score phase)
    const int myt   = (warp << 3) | (lane >> 2);  // token within tile 0..31

    const int len  = __ldg(&lengths[b]);
    const int tok0 = split * TOKSPL;
    const int ntok = min(len - tok0, TOKSPL);
    const int nact = min((len + TOKSPL - 1) / TOKSPL, NSPLIT);

    if (ntok > 0) {
        const int ntiles = (ntok + TILE - 1) / TILE;

        // warp h loads q of head h: chunk c holds dims [4c,4c+4)
        qs[warp][lane] = *(const float4*)&q[((size_t)b * HH + kvh * GG + warp) * DD + 4 * lane];

        const uint32_t smem_base = (uint32_t)__cvta_generic_to_shared(&ksm[0][0]);
        const int pbase = b * PPSS + split * PPER;

        auto issue_copy = [&](int buf, int i) {
            const int page = __ldg(&pidx[pbase + (i >> 1)]);
            const float* base = kp + ((size_t)(kvh * NPAGE + page)) * TT * DD
                                   + (size_t)(i & 1) * TILE * DD;
            #pragma unroll
            for (int j = 0; j < 8; ++j) {
                int idx = j * 128 + tid;
                int t = idx >> 5, c = idx & 31;
                uint32_t dst = smem_base
                             + (uint32_t)(buf * (TILE * 32) + t * 32 + (c ^ t)) * 16u;
                cp16(dst, base + t * DD + c * 4);
            }
            asm volatile("cp.async.commit_group;\n");
        };

        // lane state: m,l for (head=hd) over this warp's token subset
        float  m = -1e30f, l = 0.0f;
        // o0..o3: heads 0..3, dims [4*lane, 4*lane+4)  (V-phase mapping)
        float4 o0 = make_float4(0,0,0,0), o1 = o0, o2 = o0, o3 = o0;

        issue_copy(0, 0);
        if (ntiles > 1) issue_copy(1, 1);

        for (int i = 0; i < ntiles; ++i) {
            const int page_i = __ldg(&pidx[pbase + (i >> 1)]);
            const float* vb = vp + ((size_t)(kvh * NPAGE + page_i)) * TT * DD
                                 + (size_t)(i & 1) * TILE * DD;
            asm volatile("prefetch.global.L1 [%0];\n" :: "l"(vb + tid * 32));

            if (i + 1 < ntiles) asm volatile("cp.async.wait_group 1;\n");
            else                asm volatile("cp.async.wait_group 0;\n");
            __syncthreads();    // also proves all warps finished tile i-1

            if (i + 2 < ntiles) issue_copy((i + 2) % NBUF, i + 2);

            // ---- score: lane owns (token=myt, head=hd); full dot in registers ----
            const float4* kb = &ksm[i % NBUF][0];
            float4 a = make_float4(0.f, 0.f, 0.f, 0.f);
            #pragma unroll
            for (int c = 0; c < 32; ++c) {
                const float4 q4 = qs[hd][c];                // 4 distinct addrs -> 1 wf
                const float4 k4 = kb[myt * 32 + (c ^ myt)]; // 8 distinct addrs, no conflict
                a.x += q4.x * k4.x;
                a.y += q4.y * k4.y;
                a.z += q4.z * k4.z;
                a.w += q4.w * k4.w;
            }
            float s = (a.x + a.y) + (a.z + a.w);
            if (tok0 + i * TILE + myt >= len) s = -1e30f;

            // ---- softmax over warp's 8 tokens, all 4 heads at once ----
            float pm = s;
            pm = fmaxf(pm, __shfl_xor_sync(FULL, pm, 4));
            pm = fmaxf(pm, __shfl_xor_sync(FULL, pm, 8));
            pm = fmaxf(pm, __shfl_xor_sync(FULL, pm, 16));

            const float newm = fmaxf(m, pm);
            const float r = exp2f((m - newm) * L2E);
            const float e = exp2f((s - newm) * L2E);   // 0 for masked tokens
            float ls = e;
            ls += __shfl_xor_sync(FULL, ls, 4);
            ls += __shfl_xor_sync(FULL, ls, 8);
            ls += __shfl_xor_sync(FULL, ls, 16);
            l = l * r + ls;
            m = newm;

            // per-head rescale factors: lanes base..base+3 hold heads 0..3
            const int base = lane & ~3;
            const float r0 = __shfl_sync(FULL, r, base);
            const float r1 = __shfl_sync(FULL, r, base + 1);
            const float r2 = __shfl_sync(FULL, r, base + 2);
            const float r3 = __shfl_sync(FULL, r, base + 3);
            mul4(o0, r0); mul4(o1, r1); mul4(o2, r2); mul4(o3, r3);

            // publish p: lane = tok*4 + head  ->  psm[warp][tok] = (h0,h1,h2,h3)
            ((float*)psm[warp])[lane] = e;
            __syncwarp();

            // ---- V: warp reads ONLY its 8 token rows, once per CTA ----
            const float* vbl = vb + 4 * lane;   // lane = chunk now
            #pragma unroll
            for (int t = 0; t < 8; ++t) {
                const float4 p4 = psm[warp][t];
                const float4 v4 = *(const float4*)(vbl + (size_t)((warp << 3) | t) * DD);
                fma4(o0, p4.x, v4);
                fma4(o1, p4.y, v4);
                fma4(o2, p4.z, v4);
                fma4(o3, p4.w, v4);
            }
        }

        // ---- drain pipeline, then combine the 4 token-subset warps ----
        if (lane < 4) { msm[warp][lane] = m; lsm[warp][lane] = l; }
        __syncthreads();   // pipeline fully drained (wait_group 0 ran) -> osm alias safe

        float fh0, fh1, fh2, fh3, Mout = 0.f, Lout = 0.f;
        #pragma unroll
        for (int h = 0; h < 4; ++h) {
            const float M = fmaxf(fmaxf(msm[0][h], msm[1][h]),
                                  fmaxf(msm[2][h], msm[3][h]));
            float L = 0.f;
            #pragma unroll
            for (int w2 = 0; w2 < 4; ++w2)
                L += exp2f((msm[w2][h] - M) * L2E) * lsm[w2][h];
            const float f = exp2f((msm[warp][h] - M) * L2E);
            if (h == 0) fh0 = f;
            if (h == 1) fh1 = f;
            if (h == 2) fh2 = f;
            if (h == 3) fh3 = f;
            if (h == warp) { Mout = M; Lout = L; }
        }
        mul4(o0, fh0); mul4(o1, fh1); mul4(o2, fh2); mul4(o3, fh3);
        osm[warp][0][lane] = o0;
        osm[warp][1][lane] = o1;
        osm[warp][2][lane] = o2;
        osm[warp][3][lane] = o3;
        __syncthreads();

        // warp w finalizes head h = w
        float4 acc = osm[0][warp][lane];
        const float4 t1 = osm[1][warp][lane];
        const float4 t2 = osm[2][warp][lane];
        const float4 t3 = osm[3][warp][lane];
        acc.x += t1.x + t2.x + t3.x;
        acc.y += t1.y + t2.y + t3.y;
        acc.z += t1.z + t2.z + t3.z;
        acc.w += t1.w + t2.w + t3.w;

        const int slot = (split * BB + b) * HH + kvh * GG + warp;
        *(float4*)&g_o[(size_t)slot * DD + 4 * lane] = acc;
        if (lane == 0) { g_m[slot] = Mout; g_l[slot] = Lout; }
        __threadfence();
        __syncthreads();
    }

    // ---- arrival count; last CTA of (b,kvh) reduces its 4 heads ----
    if (tid == 0)
        s_last = (atomicAdd(&g_cnt[b * KVHH + kvh], 1) == NSPLIT - 1);
    __syncthreads();

    if (s_last) {
        __threadfence();   // acquire: see all split CTAs' g_* writes
        const int idx = b * HH + kvh * GG + warp;   // this warp's (b,h)

        float M = -1e30f;
        for (int j = 0; j < nact; ++j)
            M = fmaxf(M, g_m[j * BB * HH + idx]);

        float L = 0.0f;
        float4 acc = make_float4(0.f, 0.f, 0.f, 0.f);
        for (int j = 0; j < nact; ++j) {
            const int sl = j * BB * HH + idx;
            const float f = exp2f((g_m[sl] - M) * L2E);
            L += f * g_l[sl];
            float4 ov = *(const float4*)&g_o[(size_t)sl * DD + 4 * lane];
            acc.x += f * ov.x;
            acc.y += f * ov.y;
            acc.z += f * ov.z;
            acc.w += f * ov.w;
        }

        const float inv = 1.0f / L;   // split 0 always non-empty -> L > 0
        float4 res = make_float4(acc.x * inv, acc.y * inv, acc.z * inv, acc.w * inv);
        *(float4*)&out[(size_t)idx * DD + 4 * lane] = res;

        if (tid == 0) g_cnt[b * KVHH + kvh] = 0;   // reset for graph replay
    }
}

extern "C" void kernel_launch(void* const* d_in, const int* in_sizes, int n_in,
                              void* d_out, int out_size)
{
    const float* q   = (const float*)d_in[0];
    const float* kp  = (const float*)d_in[1];
    const float* vp  = (const float*)d_in[2];
    const int*   len = (const int*)d_in[3];
    const int*   pid = (const int*)d_in[4];
    float* out = (float*)d_out;

    dim3 grid(NSPLIT, KVHH, BB);
    attn_fused<<<grid, 128>>>(q, kp, vp, len, pid, out);
}

// round 17
// speedup vs baseline: 1.9031x; 1.9031x over previous
#include <cuda_runtime.h>
#include <cstdint>

// Decode-mode paged attention, fp32, GQA 4. Split-KV flash decode, fully fused.
// No-smem-K design: lane = chunk; each warp reads ONLY its 8 token rows of K and V
// directly from global (each KV byte crosses l1tex once per CTA). Scores finished by a
// 31-shuffle recursive-halving transpose-reduce. prefetch.global.L1 at distance 2.
// Last-CTA-per-(b,kvh) fused reduction.

#define BB     32
#define HH     32
#define DD     128
#define KVHH   8
#define GG     4
#define NPAGE  2048
#define TT     64
#define PPSS   64
#define NSPLIT 16
#define PPER   (PPSS / NSPLIT)     // 4 pages per split
#define TOKSPL (PPER * TT)         // 256 tokens per split
#define TILE   32                  // tokens per tile (half page)
#define L2E    1.4426950408889634f
#define FULL   0xffffffffu

__device__ float g_m[NSPLIT * BB * HH];
__device__ float g_l[NSPLIT * BB * HH];
__device__ float g_o[NSPLIT * BB * HH * DD];
__device__ int   g_cnt[BB * KVHH];          // zero-init; last CTA resets -> replay-safe

__device__ __forceinline__ float dot4(float4 a, float4 b) {
    return a.x * b.x + a.y * b.y + a.z * b.z + a.w * b.w;
}
__device__ __forceinline__ void fma4(float4& o, float p, float4 v) {
    o.x += p * v.x; o.y += p * v.y; o.z += p * v.z; o.w += p * v.w;
}
__device__ __forceinline__ void mul4(float4& o, float r) {
    o.x *= r; o.y *= r; o.z *= r; o.w *= r;
}

__global__ __launch_bounds__(128, 4)
void attn_fused(const float* __restrict__ q,
                const float* __restrict__ kp,
                const float* __restrict__ vp,
                const int*   __restrict__ lengths,
                const int*   __restrict__ pidx,
                float*       __restrict__ out)
{
    __shared__ float4 osm[GG][GG][32];            // 8 KB combine buffer
    __shared__ float  msm[GG][GG], lsm[GG][GG];   // [warp][head]
    __shared__ int    s_last;

    const int split = blockIdx.x;
    const int kvh   = blockIdx.y;
    const int b     = blockIdx.z;
    const int tid   = threadIdx.x;
    const int warp  = tid >> 5;
    const int lane  = tid & 31;
    const int st    = lane >> 2;     // score slot: token within warp's 8
    // score slot head = lane & 3

    const int len  = __ldg(&lengths[b]);
    const int tok0 = split * TOKSPL;
    const int ntok = min(len - tok0, TOKSPL);
    const int nact = min((len + TOKSPL - 1) / TOKSPL, NSPLIT);

    if (ntok > 0) {
        const int ntiles = (ntok + TILE - 1) / TILE;
        const int pbase  = b * PPSS + split * PPER;
        const size_t kvstride = (size_t)kvh * NPAGE * TT * DD;

        // q in registers: lane = chunk; qr[h] = q[head h][dims 4*lane .. 4*lane+3]
        const float* qb = &q[((size_t)b * HH + kvh * GG) * DD + 4 * lane];
        const float4 qr0 = *(const float4*)(qb);
        const float4 qr1 = *(const float4*)(qb + DD);
        const float4 qr2 = *(const float4*)(qb + 2 * DD);
        const float4 qr3 = *(const float4*)(qb + 3 * DD);

        auto tile_off = [&](int i) -> size_t {
            const int page = __ldg(&pidx[pbase + (i >> 1)]);
            return (size_t)page * TT * DD + (size_t)(i & 1) * TILE * DD;
        };
        // prefetch one 128B line per thread per array: 128 lines = 16KB tile
        auto pref = [&](size_t off) {
            asm volatile("prefetch.global.L1 [%0];\n" :: "l"(kp + kvstride + off + tid * 32));
            asm volatile("prefetch.global.L1 [%0];\n" :: "l"(vp + kvstride + off + tid * 32));
        };

        // lane softmax state: (m,l) for slot (st, head=lane&3)
        float  m = -1e30f, l = 0.0f;
        // output accumulators: heads 0..3, dims [4*lane, 4*lane+4)
        float4 o0 = make_float4(0,0,0,0), o1 = o0, o2 = o0, o3 = o0;

        pref(tile_off(0));
        if (ntiles > 1) pref(tile_off(1));

        for (int i = 0; i < ntiles; ++i) {
            if (i + 2 < ntiles) pref(tile_off(i + 2));

            const size_t off = tile_off(i);
            const float* kb = kp + kvstride + off;
            const float* vb = vp + kvstride + off;

            // ---- partials: v[t*4+h] = qr[h] . k[warp's token t] over lane's chunk ----
            const float* krow = kb + (size_t)(warp << 3) * DD + 4 * lane;
            float v[32];
            #pragma unroll
            for (int t = 0; t < 8; ++t) {
                const float4 k4 = *(const float4*)(krow + t * DD);
                v[t * 4 + 0] = dot4(qr0, k4);
                v[t * 4 + 1] = dot4(qr1, k4);
                v[t * 4 + 2] = dot4(qr2, k4);
                v[t * 4 + 3] = dot4(qr3, k4);
            }

            // ---- recursive-halving transpose-reduce: lane L ends with sum of v[L] ----
            #pragma unroll
            for (int mm = 16; mm >= 1; mm >>= 1) {
                #pragma unroll
                for (int j = 0; j < mm; ++j) {
                    const float lo = v[j], hi = v[j + mm];
                    const float send  = (lane & mm) ? lo : hi;
                    const float other = __shfl_xor_sync(FULL, send, mm);
                    v[j] = ((lane & mm) ? hi : lo) + other;
                }
            }
            float s = v[0];   // score for (token = warp*8 + st, head = lane&3)
            if (tok0 + i * TILE + (warp << 3) + st >= len) s = -1e30f;

            // ---- softmax over warp's 8 tokens, all 4 heads at once ----
            float pm = s;
            pm = fmaxf(pm, __shfl_xor_sync(FULL, pm, 4));
            pm = fmaxf(pm, __shfl_xor_sync(FULL, pm, 8));
            pm = fmaxf(pm, __shfl_xor_sync(FULL, pm, 16));

            const float newm = fmaxf(m, pm);
            const float r = exp2f((m - newm) * L2E);
            const float e = exp2f((s - newm) * L2E);   // 0 for masked tokens
            float ls = e;
            ls += __shfl_xor_sync(FULL, ls, 4);
            ls += __shfl_xor_sync(FULL, ls, 8);
            ls += __shfl_xor_sync(FULL, ls, 16);
            l = l * r + ls;
            m = newm;

            // per-head rescale: lanes 0..3 hold heads 0..3 (uniform across token-lanes)
            const float r0 = __shfl_sync(FULL, r, 0);
            const float r1 = __shfl_sync(FULL, r, 1);
            const float r2 = __shfl_sync(FULL, r, 2);
            const float r3 = __shfl_sync(FULL, r, 3);
            mul4(o0, r0); mul4(o1, r1); mul4(o2, r2); mul4(o3, r3);

            // ---- V: warp reads ONLY its 8 token rows; e broadcast by shfl ----
            const float* vrow = vb + (size_t)(warp << 3) * DD + 4 * lane;
            #pragma unroll
            for (int t = 0; t < 8; ++t) {
                const float4 v4 = *(const float4*)(vrow + t * DD);
                const float e0 = __shfl_sync(FULL, e, t * 4 + 0);
                const float e1 = __shfl_sync(FULL, e, t * 4 + 1);
                const float e2 = __shfl_sync(FULL, e, t * 4 + 2);
                const float e3 = __shfl_sync(FULL, e, t * 4 + 3);
                fma4(o0, e0, v4);
                fma4(o1, e1, v4);
                fma4(o2, e2, v4);
                fma4(o3, e3, v4);
            }
        }

        // ---- combine the 4 token-subset warps ----
        if (lane < 4) { msm[warp][lane] = m; lsm[warp][lane] = l; }
        __syncthreads();

        float fh0, fh1, fh2, fh3, Mout = 0.f, Lout = 0.f;
        #pragma unroll
        for (int h = 0; h < 4; ++h) {
            const float M = fmaxf(fmaxf(msm[0][h], msm[1][h]),
                                  fmaxf(msm[2][h], msm[3][h]));
            float L = 0.f;
            #pragma unroll
            for (int w2 = 0; w2 < 4; ++w2)
                L += exp2f((msm[w2][h] - M) * L2E) * lsm[w2][h];
            const float f = exp2f((msm[warp][h] - M) * L2E);
            if (h == 0) fh0 = f;
            if (h == 1) fh1 = f;
            if (h == 2) fh2 = f;
            if (h == 3) fh3 = f;
            if (h == warp) { Mout = M; Lout = L; }
        }
        mul4(o0, fh0); mul4(o1, fh1); mul4(o2, fh2); mul4(o3, fh3);
        osm[warp][0][lane] = o0;
        osm[warp][1][lane] = o1;
        osm[warp][2][lane] = o2;
        osm[warp][3][lane] = o3;
        __syncthreads();

        // warp w finalizes head h = w
        float4 acc = osm[0][warp][lane];
        const float4 t1 = osm[1][warp][lane];
        const float4 t2 = osm[2][warp][lane];
        const float4 t3 = osm[3][warp][lane];
        acc.x += t1.x + t2.x + t3.x;
        acc.y += t1.y + t2.y + t3.y;
        acc.z += t1.z + t2.z + t3.z;
        acc.w += t1.w + t2.w + t3.w;

        const int slot = (split * BB + b) * HH + kvh * GG + warp;
        *(float4*)&g_o[(size_t)slot * DD + 4 * lane] = acc;
        if (lane == 0) { g_m[slot] = Mout; g_l[slot] = Lout; }
        __threadfence();
        __syncthreads();
    }

    // ---- arrival count; last CTA of (b,kvh) reduces its 4 heads ----
    if (tid == 0)
        s_last = (atomicAdd(&g_cnt[b * KVHH + kvh], 1) == NSPLIT - 1);
    __syncthreads();

    if (s_last) {
        __threadfence();   // acquire: see all split CTAs' g_* writes
        const int idx = b * HH + kvh * GG + warp;   // this warp's (b,h)

        float M = -1e30f;
        for (int j = 0; j < nact; ++j)
            M = fmaxf(M, g_m[j * BB * HH + idx]);

        float L = 0.0f;
        float4 acc = make_float4(0.f, 0.f, 0.f, 0.f);
        for (int j = 0; j < nact; ++j) {
            const int sl = j * BB * HH + idx;
            const float f = exp2f((g_m[sl] - M) * L2E);
            L += f * g_l[sl];
            float4 ov = *(const float4*)&g_o[(size_t)sl * DD + 4 * lane];
            acc.x += f * ov.x;
            acc.y += f * ov.y;
            acc.z += f * ov.z;
            acc.w += f * ov.w;
        }

        const float inv = 1.0f / L;   // split 0 always non-empty -> L > 0
        float4 res = make_float4(acc.x * inv, acc.y * inv, acc.z * inv, acc.w * inv);
        *(float4*)&out[(size_t)idx * DD + 4 * lane] = res;

        if (tid == 0) g_cnt[b * KVHH + kvh] = 0;   // reset for graph replay
    }
}

extern "C" void kernel_launch(void* const* d_in, const int* in_sizes, int n_in,
                              void* d_out, int out_size)
{
    const float* q   = (const float*)d_in[0];
    const float* kp  = (const float*)d_in[1];
    const float* vp  = (const float*)d_in[2];
    const int*   len = (const int*)d_in[3];
    const int*   pid = (const int*)d_in[4];
    float* out = (float*)d_out;

    dim3 grid(NSPLIT, KVHH, BB);
    attn_fused<<<grid, 128>>>(q, kp, vp, len, pid, out);
}